// round 10
// baseline (speedup 1.0000x reference)
#include <cuda_runtime.h>
#include <cuda_bf16.h>
#include <stdint.h>

#define MAXN 50000
#define MAXE 800000
#define IN_DIM 16
#define HID 64
#define OUT 32
#define SCAN_B 256   // NB = ceil(N/256) must be <= 256

// Scratch (device globals; allocation-free per harness rules)
__device__ __align__(16) int   g_cnt   [MAXN];
__device__ __align__(16) int   g_rowptr[MAXN + 1];
__device__ __align__(16) int   g_cursor[MAXN];
__device__ __align__(16) int   g_bsum  [SCAN_B];
__device__ __align__(16) int   g_csr   [MAXE];
__device__ __align__(16) float g_dinv  [MAXN];
__device__ __align__(16) float g_y     [MAXN * IN_DIM]; // dinv_d * sum dinv_s x_s
__device__ __align__(16) float g_g2    [MAXN * OUT];    // dinv*(h@W2)

// ---------- CSR build ----------
__global__ void k_zero(int N) {
    int i = blockIdx.x * blockDim.x + threadIdx.x;
    if (i < N) g_cnt[i] = 0;
}

__global__ void k_count(const int* __restrict__ dst, int E) {
    int e = blockIdx.x * blockDim.x + threadIdx.x;
    if (e < E) atomicAdd(&g_cnt[dst[e]], 1);
}

// per-block exclusive scan of g_cnt -> g_rowptr(local), block totals -> g_bsum
__global__ void k_scan1(int N) {
    __shared__ int sh[SCAN_B];
    int i = blockIdx.x * SCAN_B + threadIdx.x;
    int v = (i < N) ? g_cnt[i] : 0;
    sh[threadIdx.x] = v;
    __syncthreads();
    for (int off = 1; off < SCAN_B; off <<= 1) {
        int t = (threadIdx.x >= off) ? sh[threadIdx.x - off] : 0;
        __syncthreads();
        sh[threadIdx.x] += t;
        __syncthreads();
    }
    if (i < N) g_rowptr[i] = sh[threadIdx.x] - v;   // exclusive (local)
    if (threadIdx.x == SCAN_B - 1) g_bsum[blockIdx.x] = sh[SCAN_B - 1];
}

// fused scan2+scan3: each block reduces bsum[0..blockIdx) itself, then
// finalizes rowptr, cursor, dinv.
__global__ void k_scan23(int N, int E, int NB) {
    __shared__ int sh[SCAN_B];
    int b = blockIdx.x;
    int partial = (threadIdx.x < b && threadIdx.x < NB) ? g_bsum[threadIdx.x] : 0;
    sh[threadIdx.x] = partial;
    __syncthreads();
    for (int off = 128; off > 0; off >>= 1) {
        if (threadIdx.x < off) sh[threadIdx.x] += sh[threadIdx.x + off];
        __syncthreads();
    }
    int prefix = sh[0];

    int i = b * SCAN_B + threadIdx.x;
    if (i < N) {
        int r = g_rowptr[i] + prefix;
        g_rowptr[i] = r;
        g_cursor[i] = r;
        g_dinv[i]   = rsqrtf((float)g_cnt[i] + 1.0f);
    }
    if (i == 0) g_rowptr[N] = E;
}

__global__ void k_fill(const int* __restrict__ src,
                       const int* __restrict__ dst, int E) {
    int e = blockIdx.x * blockDim.x + threadIdx.x;
    if (e < E) {
        int pos = atomicAdd(&g_cursor[dst[e]], 1);
        g_csr[pos] = src[e];
    }
}

// ---------- aggx: half-warp (16 lanes) per node, gather RAW x (64 B/edge)
// y_d = dinv_d * (dinv_d*x_d + sum_{s in N(d)} dinv_s * x_s)
__global__ void k_aggx(const float* __restrict__ x, int N) {
    int gt   = blockIdx.x * blockDim.x + threadIdx.x;
    int node = gt >> 4;
    int lane = gt & 15;
    if (node >= N) return;

    float dv   = g_dinv[node];
    float acc  = dv * x[node * IN_DIM + lane];   // self loop
    float acc2 = 0.0f;
    int beg = g_rowptr[node];
    int end = g_rowptr[node + 1];
    int j = beg;
    for (; j + 1 < end; j += 2) {
        int s0 = g_csr[j];
        int s1 = g_csr[j + 1];
        acc  += g_dinv[s0] * x[s0 * IN_DIM + lane];
        acc2 += g_dinv[s1] * x[s1 * IN_DIM + lane];
    }
    if (j < end) {
        int s = g_csr[j];
        acc += g_dinv[s] * x[s * IN_DIM + lane];
    }
    g_y[node * IN_DIM + lane] = dv * (acc + acc2);
}

// ---------- fused MLP: h = relu(y@W1 + b1); g2 = dinv*(h@W2)
// 256 threads = 8 warps = 8 nodes/block; warp per node
__global__ void k_mlp(const float* __restrict__ W1,
                      const float* __restrict__ b1,
                      const float* __restrict__ W2, int N) {
    __shared__ float W1s[IN_DIM * HID];    // 4 KB
    __shared__ float W2s[HID * OUT];       // 8 KB
    __shared__ float b1s[HID];
    __shared__ float ys[8][IN_DIM];
    __shared__ float hs[8][HID + 1];       // padded
    int tid = threadIdx.x;
    for (int i = tid; i < IN_DIM * HID; i += 256) W1s[i] = W1[i];
    for (int i = tid; i < HID * OUT;   i += 256) W2s[i] = W2[i];
    if (tid < HID) b1s[tid] = b1[tid];

    int w    = tid >> 5;
    int lane = tid & 31;
    int node = blockIdx.x * 8 + w;
    if (node < N && lane < IN_DIM) ys[w][lane] = g_y[node * IN_DIM + lane];
    __syncthreads();

    if (node >= N) return;

    // GEMM1 + bias + relu: lane computes h cols {lane, lane+32}
    float h0 = b1s[lane], h1 = b1s[lane + 32];
#pragma unroll
    for (int k = 0; k < IN_DIM; k++) {
        float yv = ys[w][k];
        h0 += yv * W1s[k * HID + lane];
        h1 += yv * W1s[k * HID + lane + 32];
    }
    hs[w][lane]      = fmaxf(h0, 0.0f);
    hs[w][lane + 32] = fmaxf(h1, 0.0f);
    __syncwarp();   // hs row touched only by this warp

    // GEMM2: lane computes g2 col = lane
    float acc = 0.0f;
#pragma unroll
    for (int k = 0; k < HID; k++) acc += hs[w][k] * W2s[k * OUT + lane];
    g_g2[node * OUT + lane] = acc * g_dinv[node];
}

// ---------- agg2: warp per node; out = dinv*(g2[self] + sum g2[src]) + b2
__global__ void k_agg2(const float* __restrict__ b2,
                       float* __restrict__ out, int N) {
    int gt   = blockIdx.x * blockDim.x + threadIdx.x;
    int node = gt >> 5;
    int lane = gt & 31;
    if (node >= N) return;

    float acc  = g_g2[node * OUT + lane];   // self loop
    float acc2 = 0.0f;
    int beg = g_rowptr[node];
    int end = g_rowptr[node + 1];
    int j = beg;
    for (; j + 1 < end; j += 2) {
        int s0 = g_csr[j];
        int s1 = g_csr[j + 1];
        acc  += g_g2[s0 * OUT + lane];
        acc2 += g_g2[s1 * OUT + lane];
    }
    if (j < end) {
        int s = g_csr[j];
        acc += g_g2[s * OUT + lane];
    }
    out[node * OUT + lane] = (acc + acc2) * g_dinv[node] + b2[lane];
}

extern "C" void kernel_launch(void* const* d_in, const int* in_sizes, int n_in,
                              void* d_out, int out_size) {
    const float* x   = (const float*)d_in[0];
    const int*   ei  = (const int*)d_in[1];     // int32 (JAX x64 disabled)
    const float* W1  = (const float*)d_in[2];
    const float* b1  = (const float*)d_in[3];
    const float* W2  = (const float*)d_in[4];
    const float* b2  = (const float*)d_in[5];
    float*       out = (float*)d_out;

    int N = in_sizes[0] / IN_DIM;     // 50000
    int E = in_sizes[1] / 2;          // 800000
    const int* src = ei;
    const int* dst = ei + E;
    int NB = (N + SCAN_B - 1) / SCAN_B;   // 196 <= 256

    k_zero  <<<(N + 255) / 256, 256>>>(N);
    k_count <<<(E + 255) / 256, 256>>>(dst, E);
    k_scan1 <<<NB, SCAN_B>>>(N);
    k_scan23<<<NB, SCAN_B>>>(N, E, NB);
    k_fill  <<<(E + 255) / 256, 256>>>(src, dst, E);
    k_aggx  <<<((long long)N * 16 + 255) / 256, 256>>>(x, N);
    k_mlp   <<<(N + 7) / 8, 256>>>(W1, b1, W2, N);
    k_agg2  <<<((long long)N * 32 + 255) / 256, 256>>>(b2, out, N);
}

// round 13
// speedup vs baseline: 1.0674x; 1.0674x over previous
#include <cuda_runtime.h>
#include <cuda_bf16.h>
#include <stdint.h>

#define MAXN 50000
#define MAXE 800000
#define IN_DIM 16
#define HID 64
#define OUT 32
#define SCAN_B 256   // NB = ceil(N/256) must be <= 256

#define FLAG_A (1ULL << 32)
#define FLAG_P (2ULL << 32)

// Scratch (device globals; allocation-free per harness rules)
__device__ __align__(16) int                g_cnt   [MAXN];
__device__ __align__(16) int                g_rowptr[MAXN + 1];
__device__ __align__(16) int                g_cursor[MAXN];
__device__ __align__(16) unsigned long long g_desc  [SCAN_B];  // lookback state
__device__ __align__(16) int                g_csr   [MAXE];
__device__ __align__(16) float              g_dinv  [MAXN];
__device__ __align__(16) float              g_y     [MAXN * IN_DIM];
__device__ __align__(16) float              g_g2    [MAXN * OUT];

// K1: zero cnt + lookback descriptors
__global__ void k_zero(int N, int NB) {
    int i = blockIdx.x * blockDim.x + threadIdx.x;
    if (i < N) g_cnt[i] = 0;
    if (i < NB) g_desc[i] = 0ULL;
}

// K2: deg count (int atomics)
__global__ void k_count(const int* __restrict__ dst, int E) {
    int e = blockIdx.x * blockDim.x + threadIdx.x;
    if (e < E) atomicAdd(&g_cnt[dst[e]], 1);
}

// K3: single-pass exclusive scan (decoupled lookback) + finalize
// rowptr/cursor/dinv. NB blocks; predecessors are always scheduled earlier.
__global__ void k_scan(int N, int E) {
    __shared__ int sh[SCAN_B];
    __shared__ int s_prefix;
    int b   = blockIdx.x;
    int tid = threadIdx.x;
    int i   = b * SCAN_B + tid;
    int v   = (i < N) ? g_cnt[i] : 0;

    // inclusive scan (Hillis-Steele)
    sh[tid] = v;
    __syncthreads();
    for (int off = 1; off < SCAN_B; off <<= 1) {
        int t = (tid >= off) ? sh[tid - off] : 0;
        __syncthreads();
        sh[tid] += t;
        __syncthreads();
    }
    int incl  = sh[tid];
    int total = sh[SCAN_B - 1];

    if (tid == 0) {
        if (b == 0) {
            atomicExch(&g_desc[0], FLAG_P | (unsigned)total);
            s_prefix = 0;
        } else {
            atomicExch(&g_desc[b], FLAG_A | (unsigned)total);
            int running = 0;
            for (int p = b - 1; p >= 0; p--) {
                unsigned long long st;
                do { st = atomicAdd(&g_desc[p], 0ULL); } while ((st >> 32) == 0);
                running += (int)(unsigned)st;
                if (st & FLAG_P) break;
            }
            atomicExch(&g_desc[b], FLAG_P | (unsigned)(running + total));
            s_prefix = running;
        }
    }
    __syncthreads();
    int prefix = s_prefix;

    if (i < N) {
        int r = prefix + incl - v;   // exclusive global
        g_rowptr[i] = r;
        g_cursor[i] = r;
        g_dinv[i]   = rsqrtf((float)v + 1.0f);
    }
    if (i == 0) g_rowptr[N] = E;
}

// K4: CSR fill
__global__ void k_fill(const int* __restrict__ src,
                       const int* __restrict__ dst, int E) {
    int e = blockIdx.x * blockDim.x + threadIdx.x;
    if (e < E) {
        int pos = atomicAdd(&g_cursor[dst[e]], 1);
        g_csr[pos] = src[e];
    }
}

// K5: aggx: half-warp per node, gather RAW x (64 B/edge)
// y_d = dinv_d * (dinv_d*x_d + sum_s dinv_s * x_s)
__global__ void k_aggx(const float* __restrict__ x, int N) {
    int gt   = blockIdx.x * blockDim.x + threadIdx.x;
    int node = gt >> 4;
    int lane = gt & 15;
    if (node >= N) return;

    float dv   = g_dinv[node];
    float acc  = dv * x[node * IN_DIM + lane];   // self loop
    float acc2 = 0.0f;
    int beg = g_rowptr[node];
    int end = g_rowptr[node + 1];
    int j = beg;
    for (; j + 1 < end; j += 2) {
        int s0 = g_csr[j];
        int s1 = g_csr[j + 1];
        acc  += g_dinv[s0] * x[s0 * IN_DIM + lane];
        acc2 += g_dinv[s1] * x[s1 * IN_DIM + lane];
    }
    if (j < end) {
        int s = g_csr[j];
        acc += g_dinv[s] * x[s * IN_DIM + lane];
    }
    g_y[node * IN_DIM + lane] = dv * (acc + acc2);
}

// K6: fused MLP: h = relu(y@W1+b1); g2 = dinv*(h@W2)
// 256 threads = 8 warps; each warp does 4 nodes => 32 nodes/block.
// h lives in registers, broadcast via shfl (no smem round-trip).
__global__ void k_mlp(const float* __restrict__ W1,
                      const float* __restrict__ b1,
                      const float* __restrict__ W2, int N) {
    __shared__ float W1s[IN_DIM * HID];   // 4 KB
    __shared__ float W2s[HID * OUT];      // 8 KB
    __shared__ float b1s[HID];
    int tid = threadIdx.x;
    for (int i = tid; i < IN_DIM * HID; i += 256) W1s[i] = W1[i];
    for (int i = tid; i < HID * OUT;   i += 256) W2s[i] = W2[i];
    if (tid < HID) b1s[tid] = b1[tid];
    __syncthreads();

    int w    = tid >> 5;
    int lane = tid & 31;
    int node0 = blockIdx.x * 32 + w * 4;

#pragma unroll
    for (int it = 0; it < 4; it++) {
        int node = node0 + it;
        if (node >= N) break;

        float yv = (lane < IN_DIM) ? g_y[node * IN_DIM + lane] : 0.0f;

        float h0 = b1s[lane], h1 = b1s[lane + 32];
#pragma unroll
        for (int k = 0; k < IN_DIM; k++) {
            float yk = __shfl_sync(0xffffffffu, yv, k);
            h0 += yk * W1s[k * HID + lane];
            h1 += yk * W1s[k * HID + lane + 32];
        }
        h0 = fmaxf(h0, 0.0f);
        h1 = fmaxf(h1, 0.0f);

        float acc = 0.0f;
#pragma unroll
        for (int k = 0; k < 32; k++) {
            float hk = __shfl_sync(0xffffffffu, h0, k);
            acc += hk * W2s[k * OUT + lane];
        }
#pragma unroll
        for (int k = 0; k < 32; k++) {
            float hk = __shfl_sync(0xffffffffu, h1, k);
            acc += hk * W2s[(k + 32) * OUT + lane];
        }
        g_g2[node * OUT + lane] = acc * g_dinv[node];
    }
}

// K7: agg2: warp per node; out = dinv*(g2[self] + sum g2[src]) + b2
__global__ void k_agg2(const float* __restrict__ b2,
                       float* __restrict__ out, int N) {
    int gt   = blockIdx.x * blockDim.x + threadIdx.x;
    int node = gt >> 5;
    int lane = gt & 31;
    if (node >= N) return;

    float acc  = g_g2[node * OUT + lane];   // self loop
    float acc2 = 0.0f;
    int beg = g_rowptr[node];
    int end = g_rowptr[node + 1];
    int j = beg;
    for (; j + 1 < end; j += 2) {
        int s0 = g_csr[j];
        int s1 = g_csr[j + 1];
        acc  += g_g2[s0 * OUT + lane];
        acc2 += g_g2[s1 * OUT + lane];
    }
    if (j < end) {
        int s = g_csr[j];
        acc += g_g2[s * OUT + lane];
    }
    out[node * OUT + lane] = (acc + acc2) * g_dinv[node] + b2[lane];
}

extern "C" void kernel_launch(void* const* d_in, const int* in_sizes, int n_in,
                              void* d_out, int out_size) {
    const float* x   = (const float*)d_in[0];
    const int*   ei  = (const int*)d_in[1];     // int32 (JAX x64 disabled)
    const float* W1  = (const float*)d_in[2];
    const float* b1  = (const float*)d_in[3];
    const float* W2  = (const float*)d_in[4];
    const float* b2  = (const float*)d_in[5];
    float*       out = (float*)d_out;

    int N = in_sizes[0] / IN_DIM;     // 50000
    int E = in_sizes[1] / 2;          // 800000
    const int* src = ei;
    const int* dst = ei + E;
    int NB = (N + SCAN_B - 1) / SCAN_B;   // 196 <= 256

    k_zero <<<(N + 255) / 256, 256>>>(N, NB);
    k_count<<<(E + 255) / 256, 256>>>(dst, E);
    k_scan <<<NB, SCAN_B>>>(N, E);
    k_fill <<<(E + 255) / 256, 256>>>(src, dst, E);
    k_aggx <<<((long long)N * 16 + 255) / 256, 256>>>(x, N);
    k_mlp  <<<(N + 31) / 32, 256>>>(W1, b1, W2, N);
    k_agg2 <<<((long long)N * 32 + 255) / 256, 256>>>(b2, out, N);
}